// round 9
// baseline (speedup 1.0000x reference)
#include <cuda_runtime.h>
#include <cstdint>

// Problem constants (fixed by the reference): N=262144 output rows, D=128.
#define MAX_N 262144
#define ROWS_PER_BLOCK 8   // 8 warps/block, warp-per-row

// Scratch: segment start offsets, g_start[n] = lower_bound(sorted_index, n).
// N+1 entries. Static __device__ global (no allocation allowed).
__device__ int g_start[MAX_N + 1];

// Kernel 1: binary search per output row.
// sorted_index is int32 (JAX x64 disabled downgrades jnp.int64 -> int32).
__global__ void compute_bounds_kernel(const int* __restrict__ idx,
                                      int M, int Nrows) {
    int n = blockIdx.x * blockDim.x + threadIdx.x;
    if (n > Nrows) return;
    int lo = 0, hi = M;
    // lower_bound: first position where idx[pos] >= n
    while (lo < hi) {
        int mid = (lo + hi) >> 1;
        if (idx[mid] < n) lo = mid + 1;
        else hi = mid;
    }
    g_start[n] = lo;
}

// Kernel 2: warp-per-row segmented sum. D=128 floats = 32 float4 = one per lane.
__global__ void __launch_bounds__(32 * ROWS_PER_BLOCK)
scatter_add_rows_kernel(const float4* __restrict__ self_t,
                        const float4* __restrict__ value,
                        float4* __restrict__ out,
                        int Nrows) {
    int row  = blockIdx.x * ROWS_PER_BLOCK + (threadIdx.x >> 5);
    int lane = threadIdx.x & 31;
    if (row >= Nrows) return;

    int s = g_start[row];
    int e = g_start[row + 1];

    int base = row * 32 + lane;           // N*32 = 8.4M, fits int
    float4 acc = self_t[base];

    for (int i = s; i < e; i++) {
        float4 v = __ldg(&value[(size_t)i * 32 + lane]);
        acc.x += v.x;
        acc.y += v.y;
        acc.z += v.z;
        acc.w += v.w;
    }
    out[base] = acc;
}

extern "C" void kernel_launch(void* const* d_in, const int* in_sizes, int n_in,
                              void* d_out, int out_size) {
    const float* self_t = (const float*)d_in[0];   // [N, 128] f32
    const float* value  = (const float*)d_in[1];   // [M, 128] f32
    const int*   sidx   = (const int*)d_in[2];     // [M] int32 (sorted)
    // d_in[3] = pos, unused

    int Nrows = in_sizes[0] / 128;   // 262144
    int M     = in_sizes[2];         // 1048576

    // Kernel 1: fill g_start[0..Nrows]
    {
        int threads = 256;
        int total = Nrows + 1;
        int blocks = (total + threads - 1) / threads;
        compute_bounds_kernel<<<blocks, threads>>>(sidx, M, Nrows);
    }

    // Kernel 2: streaming segmented add, warp per output row
    {
        int threads = 32 * ROWS_PER_BLOCK;
        int blocks = (Nrows + ROWS_PER_BLOCK - 1) / ROWS_PER_BLOCK;
        scatter_add_rows_kernel<<<blocks, threads>>>(
            (const float4*)self_t, (const float4*)value,
            (float4*)d_out, Nrows);
    }
}